// round 14
// baseline (speedup 1.0000x reference)
#include <cuda_runtime.h>
#include <cuda_fp16.h>
#include <cstdint>
#include <math.h>

// Problem constants
#define BATCH   2
#define NSEQ    2048
#define CDIM    768
#define HEADS_H 12
#define DHEAD   64
#define TOKENS  (BATCH * NSEQ)          // 4096
#define C3      (3 * CDIM)              // 2304
#define BH      (BATCH * HEADS_H)       // 24
#define MCH     16                      // moments token-split chunks

#define SCALE_F 0.125f
#define STEP_F  0.1f
#define LAMBD_F 0.5f
#define EPS_F   1e-12f

// Scratch (static device globals — no allocation)
__device__ __half g_qkvh[TOKENS * C3];  // qkv in fp16 (raw; norm fused downstream)
__device__ __half g_mparth[MCH * BH * 3 * DHEAD * DHEAD];   // fp16 partials
__device__ float  g_mc[BH * DHEAD * DHEAD];
__device__ __half g_aoh[TOKENS * CDIM];     // fp16, K-permuted
__device__ __half g_xh[TOKENS * CDIM];      // fp16, K-permuted
__device__ __half g_wqkvh[C3 * CDIM];
__device__ __half g_wprojh[CDIM * CDIM];

__device__ __forceinline__ uint32_t f2tf32(float f) {
    uint32_t u;
    asm("cvt.rna.tf32.f32 %0, %1;" : "=r"(u) : "f"(f));
    return u;
}
__device__ __forceinline__ float rtf(float f) {
    return __uint_as_float(f2tf32(f));
}
__device__ __forceinline__ uint32_t smem_u32(const void* p) {
    uint32_t a;
    asm("{ .reg .u64 t; cvta.to.shared.u64 t, %1; cvt.u32.u64 %0, t; }"
        : "=r"(a) : "l"(p));
    return a;
}
__device__ __forceinline__ uint32_t h2u(float a, float b) {
    __half2 h = __floats2half2_rn(a, b);
    return *reinterpret_cast<uint32_t*>(&h);
}
__device__ __forceinline__ float2 u2f2(uint32_t u) {
    return __half22float2(*reinterpret_cast<__half2*>(&u));
}
__device__ __forceinline__ void ldsm_x4_trans(
    uint32_t& r0, uint32_t& r1, uint32_t& r2, uint32_t& r3, uint32_t addr)
{
    asm volatile("ldmatrix.sync.aligned.m8n8.x4.trans.shared.b16 "
                 "{%0,%1,%2,%3}, [%4];"
                 : "=r"(r0), "=r"(r1), "=r"(r2), "=r"(r3) : "r"(addr));
}

// fp16 m16n8k16 MMA, fp32 accumulate
__device__ __forceinline__ void mma_f16_16x8x16(
    float& c0, float& c1, float& c2, float& c3,
    uint32_t a0, uint32_t a1, uint32_t a2, uint32_t a3,
    uint32_t b0, uint32_t b1)
{
    asm volatile(
        "mma.sync.aligned.m16n8k16.row.col.f32.f16.f16.f32 "
        "{%0,%1,%2,%3}, {%4,%5,%6,%7}, {%8,%9}, {%0,%1,%2,%3};"
        : "+f"(c0), "+f"(c1), "+f"(c2), "+f"(c3)
        : "r"(a0), "r"(a1), "r"(a2), "r"(a3), "r"(b0), "r"(b1));
}
// tf32 m16n8k8 MMA (outhead path)
__device__ __forceinline__ void mma_tf32_16x8x8(
    float& c0, float& c1, float& c2, float& c3,
    uint32_t a0, uint32_t a1, uint32_t a2, uint32_t a3,
    uint32_t b0, uint32_t b1)
{
    asm volatile(
        "mma.sync.aligned.m16n8k8.row.col.f32.tf32.tf32.f32 "
        "{%0,%1,%2,%3}, {%4,%5,%6,%7}, {%8,%9}, {%0,%1,%2,%3};"
        : "+f"(c0), "+f"(c1), "+f"(c2), "+f"(c3)
        : "r"(a0), "r"(a1), "r"(a2), "r"(a3), "r"(b0), "r"(b1));
}

// ---------------------------------------------------------------------------
// Fused fp32->fp16 convert + 16-wide K-permute for x, Wqkv, Wproj.
// Output order per 16-group: [0,1,8,9,2,3,10,11,4,5,12,13,6,7,14,15]
// ---------------------------------------------------------------------------
#define HG1 (TOKENS * CDIM / 16)             // 196608
#define HG2 (HG1 + C3 * CDIM / 16)           // 307200
#define HG3 (HG2 + CDIM * CDIM / 16)         // 344064

__global__ void __launch_bounds__(256) round_perm_kernel(
    const float* __restrict__ x, const float* __restrict__ wq,
    const float* __restrict__ wp)
{
    const int gidx = blockIdx.x * 256 + threadIdx.x;
    const float* src; __half* dst; int off;
    if (gidx < HG1)      { src = x;  dst = g_xh;     off = gidx; }
    else if (gidx < HG2) { src = wq; dst = g_wqkvh;  off = gidx - HG1; }
    else if (gidx < HG3) { src = wp; dst = g_wprojh; off = gidx - HG2; }
    else return;

    const float4* s4 = (const float4*)(src) + off * 4;
    const float4 f0 = s4[0];
    const float4 f1 = s4[1];
    const float4 f2 = s4[2];
    const float4 f3 = s4[3];

    uint4 u0, u1;
    u0.x = h2u(f0.x, f0.y);  u0.y = h2u(f2.x, f2.y);
    u0.z = h2u(f0.z, f0.w);  u0.w = h2u(f2.z, f2.w);
    u1.x = h2u(f1.x, f1.y);  u1.y = h2u(f3.x, f3.y);
    u1.z = h2u(f1.z, f1.w);  u1.w = h2u(f3.z, f3.w);
    uint4* d4 = (uint4*)(dst + (size_t)off * 16);
    d4[0] = u0;
    d4[1] = u1;
}

// ---------------------------------------------------------------------------
// fp16 mma.sync NT GEMM, cp.async 4-stage pipeline, K-PERMUTED fp16 operands.
// CTA 128xNT, 4 warps, warp tile 64x(NT/2), K-chunk 32, pitch 48 halves.
// HOUT=true: write fp16 (no bias). HOUT=false: write fp32 (+bias).
// ---------------------------------------------------------------------------
#define HP        48
#define HSTAGES   4
#define HGSMEM(NT) (HSTAGES * (128 + (NT)) * HP * 2)

template<bool HOUT, int NT>
__global__ void __launch_bounds__(128, 2) gemm_f16_pipe(
    const __half* __restrict__ A, const __half* __restrict__ Bw,
    const float* __restrict__ bias, void* __restrict__ Cv,
    int M, int N, int K)
{
    constexpr int NI     = NT / 16;            // ni count per warp
    constexpr int ASTG_B = 128 * HP * 2;       // A stage bytes
    constexpr int BSTG_B = NT * HP * 2;        // B stage bytes

    extern __shared__ __half hsm[];
    __half* As = hsm;
    __half* Bs = hsm + HSTAGES * 128 * HP;

    const int tid  = threadIdx.x;
    const int wid  = tid >> 5;
    const int lane = tid & 31;
    const int g    = lane >> 2;
    const int t    = lane & 3;
    const int row0 = blockIdx.y * 128;
    const int col0 = blockIdx.x * NT;
    const int wm0  = (wid >> 1) * 64;
    const int wn0  = (wid & 1) * (NT / 2);

    float acc[4][NI][4];
    #pragma unroll
    for (int mi = 0; mi < 4; mi++)
        #pragma unroll
        for (int ni = 0; ni < NI; ni++)
            #pragma unroll
            for (int c = 0; c < 4; c++) acc[mi][ni][c] = 0.0f;

    const int lrow = tid >> 2;            // 0..31
    const int lseg = (tid & 3) << 3;      // 0,8,16,24 halves

    const __half* aptr = A  + (size_t)(row0 + lrow) * K + lseg;
    const __half* bptr = Bw + (size_t)(col0 + lrow) * K + lseg;
    const uint32_t a_sb = smem_u32(As) + (lrow * HP + lseg) * 2;
    const uint32_t b_sb = smem_u32(Bs) + (lrow * HP + lseg) * 2;

    const int nc = K >> 5;

    #pragma unroll
    for (int s = 0; s < HSTAGES - 1; s++) {
        const int k0 = s << 5;
        #pragma unroll
        for (int i = 0; i < 4; i++) {
            asm volatile("cp.async.cg.shared.global [%0], [%1], 16;"
                :: "r"(a_sb + s * ASTG_B + i * 32 * HP * 2),
                   "l"(aptr + (size_t)i * 32 * K + k0) : "memory");
        }
        #pragma unroll
        for (int i = 0; i < NT / 32; i++) {
            asm volatile("cp.async.cg.shared.global [%0], [%1], 16;"
                :: "r"(b_sb + s * BSTG_B + i * 32 * HP * 2),
                   "l"(bptr + (size_t)i * 32 * K + k0) : "memory");
        }
        asm volatile("cp.async.commit_group;" ::: "memory");
    }

    for (int c = 0; c < nc; c++) {
        asm volatile("cp.async.wait_group %0;" :: "n"(HSTAGES - 2) : "memory");
        __syncthreads();

        const int cn = c + HSTAGES - 1;
        if (cn < nc) {
            const int s  = cn & (HSTAGES - 1);
            const int k0 = cn << 5;
            #pragma unroll
            for (int i = 0; i < 4; i++) {
                asm volatile("cp.async.cg.shared.global [%0], [%1], 16;"
                    :: "r"(a_sb + s * ASTG_B + i * 32 * HP * 2),
                       "l"(aptr + (size_t)i * 32 * K + k0) : "memory");
            }
            #pragma unroll
            for (int i = 0; i < NT / 32; i++) {
                asm volatile("cp.async.cg.shared.global [%0], [%1], 16;"
                    :: "r"(b_sb + s * BSTG_B + i * 32 * HP * 2),
                       "l"(bptr + (size_t)i * 32 * K + k0) : "memory");
            }
        }
        asm volatile("cp.async.commit_group;" ::: "memory");

        const __half* as = As + (c & (HSTAGES - 1)) * 128 * HP;
        const __half* bs = Bs + (c & (HSTAGES - 1)) * NT * HP;
        #pragma unroll
        for (int kk = 0; kk < 2; kk++) {
            const int ko = kk * 16 + t * 4;
            uint32_t af[4][4], bf[NI][2];
            #pragma unroll
            for (int mi = 0; mi < 4; mi++) {
                const int mrow = wm0 + mi * 16;
                const uint2 av0 = *(const uint2*)(as + (mrow + g)     * HP + ko);
                const uint2 av1 = *(const uint2*)(as + (mrow + g + 8) * HP + ko);
                af[mi][0] = av0.x; af[mi][2] = av0.y;
                af[mi][1] = av1.x; af[mi][3] = av1.y;
            }
            #pragma unroll
            for (int ni = 0; ni < NI; ni++) {
                const uint2 bv = *(const uint2*)(bs + (wn0 + ni * 8 + g) * HP + ko);
                bf[ni][0] = bv.x; bf[ni][1] = bv.y;
            }
            #pragma unroll
            for (int mi = 0; mi < 4; mi++)
                #pragma unroll
                for (int ni = 0; ni < NI; ni++)
                    mma_f16_16x8x16(acc[mi][ni][0], acc[mi][ni][1],
                                    acc[mi][ni][2], acc[mi][ni][3],
                                    af[mi][0], af[mi][1], af[mi][2], af[mi][3],
                                    bf[ni][0], bf[ni][1]);
        }
    }

    #pragma unroll
    for (int mi = 0; mi < 4; mi++) {
        #pragma unroll
        for (int ni = 0; ni < NI; ni++) {
            const int col = col0 + wn0 + ni * 8 + 2 * t;
            const int r0 = row0 + wm0 + mi * 16 + g;
            if (HOUT) {
                __half* C = (__half*)Cv;
                *(__half2*)(C + (size_t)r0 * N + col) =
                    __floats2half2_rn(acc[mi][ni][0], acc[mi][ni][1]);
                *(__half2*)(C + (size_t)(r0 + 8) * N + col) =
                    __floats2half2_rn(acc[mi][ni][2], acc[mi][ni][3]);
            } else {
                float* C = (float*)Cv;
                float b0 = 0.f, b1 = 0.f;
                if (bias) { b0 = bias[col]; b1 = bias[col + 1]; }
                *(float2*)(C + (size_t)r0 * N + col) =
                    make_float2(acc[mi][ni][0] + b0, acc[mi][ni][1] + b1);
                *(float2*)(C + (size_t)(r0 + 8) * N + col) =
                    make_float2(acc[mi][ni][2] + b0, acc[mi][ni][3] + b1);
            }
        }
    }
}

// ---------------------------------------------------------------------------
// Moments via fp16 mma + ldmatrix.trans, FUSED q/k L2-normalization.
// grid (BH, MCH), 192 threads. fp16 partials to g_mparth. (unchanged R13)
// ---------------------------------------------------------------------------
#define MTOK (NSEQ / MCH)                // 128 tokens per chunk
#define MNIT (MTOK / 32)                 // 4 iters of 32 tokens
#define TPITCH 72                        // halves per smem row

__global__ void __launch_bounds__(192, 2) moments_mma_kernel()
{
    __shared__ __half TQ[2][32][TPITCH];
    __shared__ __half TK[2][32][TPITCH];
    __shared__ __half TV[2][32][TPITCH];

    const int bh = blockIdx.x;
    const int ch = blockIdx.y;
    const int b = bh / HEADS_H, h = bh % HEADS_H;
    const int tid  = threadIdx.x;
    const int wid  = tid >> 5;
    const int lane = tid & 31;
    const int g    = lane >> 2;
    const int t    = lane & 3;
    const int o    = wid >> 1;
    const int mhalf = (wid & 1) * 32;

    const int mat  = tid >> 6;
    const int trow = (tid & 63) >> 1;
    const int dh   = (tid & 1) * 32;

    const size_t base = (size_t)(b * NSEQ + ch * MTOK) * C3
                      + mat * 768 + h * 64 + dh;

    const int a_tok = ((lane >> 4) << 3) + (lane & 7);
    const int a_d   = ((lane >> 3) & 1) << 3;
    const int b_tok = (((lane >> 3) & 1) << 3) + (lane & 7);
    const int b_d   = (lane >> 4) << 3;

    float acc[2][8][4];
    #pragma unroll
    for (int mi = 0; mi < 2; mi++)
        #pragma unroll
        for (int ni = 0; ni < 8; ni++)
            #pragma unroll
            for (int c = 0; c < 4; c++) acc[mi][ni][c] = 0.0f;

    uint4 r[4];
    {
        const __half* src = g_qkvh + base + (size_t)trow * C3;
        #pragma unroll
        for (int j = 0; j < 4; j++) r[j] = ((const uint4*)src)[j];
    }

    for (int it = 0; it < MNIT; it++) {
        float inv = 1.0f;
        if (mat < 2) {
            float ss = 0.f;
            #pragma unroll
            for (int j = 0; j < 4; j++) {
                const uint32_t* u = &r[j].x;
                #pragma unroll
                for (int q = 0; q < 4; q++) {
                    const float2 f = u2f2(u[q]);
                    ss += f.x * f.x + f.y * f.y;
                }
            }
            ss += __shfl_xor_sync(0xffffffffu, ss, 1);
            inv = 1.0f / fmaxf(sqrtf(ss), EPS_F);
        }
        {
            __half* Td = ((mat == 0) ? TQ[it & 1]
                        : (mat == 1) ? TK[it & 1] : TV[it & 1])[trow] + dh;
            #pragma unroll
            for (int j = 0; j < 4; j++) {
                const uint32_t* u = &r[j].x;
                uint4 w;
                const float2 f0 = u2f2(u[0]);
                const float2 f1 = u2f2(u[1]);
                const float2 f2 = u2f2(u[2]);
                const float2 f3 = u2f2(u[3]);
                w.x = h2u(f0.x * inv, f0.y * inv);
                w.y = h2u(f1.x * inv, f1.y * inv);
                w.z = h2u(f2.x * inv, f2.y * inv);
                w.w = h2u(f3.x * inv, f3.y * inv);
                ((uint4*)Td)[j] = w;
            }
        }
        uint4 rn[4];
        if (it + 1 < MNIT) {
            const __half* src = g_qkvh + base + (size_t)((it + 1) * 32 + trow) * C3;
            #pragma unroll
            for (int j = 0; j < 4; j++) rn[j] = ((const uint4*)src)[j];
        }
        __syncthreads();

        const uint32_t am = smem_u32((o == 0) ? TK[it & 1] : TQ[it & 1]);
        const uint32_t bm = smem_u32((o == 2) ? TQ[it & 1] : TV[it & 1]);
        #pragma unroll
        for (int ks = 0; ks < 2; ks++) {
            const int tokb = ks * 16;
            uint32_t af[2][4], bf[8][2];
            #pragma unroll
            for (int mi = 0; mi < 2; mi++) {
                const uint32_t addr = am +
                    ((tokb + a_tok) * TPITCH + mhalf + mi * 16 + a_d) * 2;
                ldsm_x4_trans(af[mi][0], af[mi][1], af[mi][2], af[mi][3], addr);
            }
            #pragma unroll
            for (int j = 0; j < 4; j++) {
                const uint32_t addr = bm +
                    ((tokb + b_tok) * TPITCH + j * 16 + b_d) * 2;
                ldsm_x4_trans(bf[2 * j][0], bf[2 * j][1],
                              bf[2 * j + 1][0], bf[2 * j + 1][1], addr);
            }
            #pragma unroll
            for (int mi = 0; mi < 2; mi++)
                #pragma unroll
                for (int ni = 0; ni < 8; ni++)
                    mma_f16_16x8x16(acc[mi][ni][0], acc[mi][ni][1],
                                    acc[mi][ni][2], acc[mi][ni][3],
                                    af[mi][0], af[mi][1], af[mi][2], af[mi][3],
                                    bf[ni][0], bf[ni][1]);
        }
        #pragma unroll
        for (int j = 0; j < 4; j++) r[j] = rn[j];
    }

    __half* outp = g_mparth + ((size_t)(ch * BH + bh) * 3 + o) * 4096;
    #pragma unroll
    for (int mi = 0; mi < 2; mi++) {
        #pragma unroll
        for (int ni = 0; ni < 8; ni++) {
            const int row = mhalf + mi * 16 + g;
            const int col = ni * 8 + 2 * t;
            *(__half2*)(outp + row * 64 + col) =
                __floats2half2_rn(acc[mi][ni][0], acc[mi][ni][1]);
            *(__half2*)(outp + (row + 8) * 64 + col) =
                __floats2half2_rn(acc[mi][ni][2], acc[mi][ni][3]);
        }
    }
}

// ---------------------------------------------------------------------------
// FUSED reduce + combine: per head, sum fp16 partials over MCH chunks into
// smem, then Mc = STEP*(SCALE*M2 - SCALE^2*M3@M1). grid BH, 256 threads.
// ---------------------------------------------------------------------------
__global__ void __launch_bounds__(256) combine_fused_kernel()
{
    const int bh  = blockIdx.x;
    const int tid = threadIdx.x;
    __shared__ float m1s[4096];
    __shared__ float m2s[4096];
    __shared__ float m3s[4096];

    // Phase 1: reduce. Head block = 12288 halves = 1536 uint4; 6 per thread.
    const __half* pbase = g_mparth + (size_t)bh * 3 * 4096;
    #pragma unroll
    for (int i = 0; i < 6; i++) {
        const int u4 = tid + i * 256;     // 0..1535
        float s[8];
        #pragma unroll
        for (int j = 0; j < 8; j++) s[j] = 0.f;
        #pragma unroll
        for (int ch = 0; ch < MCH; ch++) {
            const uint4 v = ((const uint4*)(pbase + (size_t)ch * BH * 3 * 4096))[u4];
            const uint32_t* u = &v.x;
            #pragma unroll
            for (int q = 0; q < 4; q++) {
                const float2 f = u2f2(u[q]);
                s[q * 2]     += f.x;
                s[q * 2 + 1] += f.y;
            }
        }
        const int e = u4 * 8;             // element index 0..12287 (8-aligned)
        float* dstS = (e < 4096) ? (m1s + e)
                    : (e < 8192) ? (m2s + e - 4096) : (m3s + e - 8192);
        #pragma unroll
        for (int j = 0; j < 8; j++) dstS[j] = s[j];
    }
    __syncthreads();

    // Phase 2: combine.
    const int tr = tid >> 4, tc = tid & 15;
    float p[4][4];
    #pragma unroll
    for (int i = 0; i < 4; i++)
        #pragma unroll
        for (int j = 0; j < 4; j++) p[i][j] = 0.f;

    for (int e = 0; e < 64; e++) {
        float a[4], bb[4];
        #pragma unroll
        for (int i = 0; i < 4; i++) a[i] = m3s[(tr * 4 + i) * 64 + e];
        #pragma unroll
        for (int j = 0; j < 4; j++) bb[j] = m1s[e * 64 + tc * 4 + j];
        #pragma unroll
        for (int i = 0; i < 4; i++)
            #pragma unroll
            for (int j = 0; j < 4; j++) p[i][j] += a[i] * bb[j];
    }

    const float c1 = STEP_F * SCALE_F;
    const float c2 = STEP_F * SCALE_F * SCALE_F;
    #pragma unroll
    for (int i = 0; i < 4; i++)
        #pragma unroll
        for (int j = 0; j < 4; j++) {
            const int idx = (tr * 4 + i) * 64 + (tc * 4 + j);
            g_mc[(size_t)bh * 4096 + idx] = c1 * m2s[idx] - c2 * p[i][j];
        }
}

// ---------------------------------------------------------------------------
// outhead via tf32 mma with FUSED K-normalization; fp16 qkv input.
// Output: fp16 K-permuted (16-wide perm) half2 stores into g_aoh.
// ---------------------------------------------------------------------------
#define OH_KPITCH   68
#define OH_KS_FL    (128 * OH_KPITCH)
#define OH_MC_FL    (64 * OH_KPITCH)
#define OH_SMEM_BYTES ((OH_KS_FL + OH_MC_FL) * 4)   // 52224

__global__ void __launch_bounds__(128) outhead_mma_kernel()
{
    extern __shared__ float osm[];
    float* Ks  = osm;
    float* McT = osm + OH_KS_FL;

    const int bh   = blockIdx.y;
    const int tile = blockIdx.x;
    const int b = bh / HEADS_H, h = bh % HEADS_H;
    const int tid  = threadIdx.x;
    const int wid  = tid >> 5;
    const int lane = tid & 31;
    const int g    = lane >> 2;
    const int t    = lane & 3;
    const int n0   = tile * 128;

    {
        const int d1  = tid >> 1;
        const int d2g = (tid & 1) * 32;
        const float* src = g_mc + (size_t)bh * 4096 + d1 * 64 + d2g;
        #pragma unroll
        for (int j = 0; j < 8; j++) {
            float4 v = *(const float4*)(src + j * 4);
            McT[(d2g + j * 4 + 0) * OH_KPITCH + d1] = rtf(v.x);
            McT[(d2g + j * 4 + 1) * OH_KPITCH + d1] = rtf(v.y);
            McT[(d2g + j * 4 + 2) * OH_KPITCH + d1] = rtf(v.z);
            McT[(d2g + j * 4 + 3) * OH_KPITCH + d1] = rtf(v.w);
        }
    }
    {
        const __half* src = g_qkvh + (size_t)(b * NSEQ + n0 + tid) * C3 + 768 + h * 64;
        float kv[64];
        float ss = 0.f;
        #pragma unroll
        for (int j = 0; j < 8; j++) {
            const uint4 r = *(const uint4*)(src + j * 8);
            const uint32_t* u = &r.x;
            #pragma unroll
            for (int q = 0; q < 4; q++) {
                const float2 f = u2f2(u[q]);
                kv[j * 8 + q * 2]     = f.x;
                kv[j * 8 + q * 2 + 1] = f.y;
                ss += f.x * f.x + f.y * f.y;
            }
        }
        const float inv = 1.0f / fmaxf(sqrtf(ss), EPS_F);
        #pragma unroll
        for (int j = 0; j < 64; j++)
            Ks[tid * OH_KPITCH + j] = rtf(kv[j] * inv);
    }
    __syncthreads();

    const int mrow0 = wid * 32;
    float acc[2][8][4];
    #pragma unroll
    for (int mi = 0; mi < 2; mi++)
        #pragma unroll
        for (int ni = 0; ni < 8; ni++)
            #pragma unroll
            for (int c = 0; c < 4; c++) acc[mi][ni][c] = 0.0f;

    #pragma unroll
    for (int kk = 0; kk < 64; kk += 8) {
        uint32_t af[2][4], bf[8][2];
        #pragma unroll
        for (int mi = 0; mi < 2; mi++) {
            const int mrow = mrow0 + mi * 16;
            af[mi][0] = __float_as_uint(Ks[(mrow + g)     * OH_KPITCH + kk + t]);
            af[mi][1] = __float_as_uint(Ks[(mrow + g + 8) * OH_KPITCH + kk + t]);
            af[mi][2] = __float_as_uint(Ks[(mrow + g)     * OH_KPITCH + kk + t + 4]);
            af[mi][3] = __float_as_uint(Ks[(mrow + g + 8) * OH_KPITCH + kk + t + 4]);
        }
        #pragma unroll
        for (int ni = 0; ni < 8; ni++) {
            bf[ni][0] = __float_as_uint(McT[(ni * 8 + g) * OH_KPITCH + kk + t]);
            bf[ni][1] = __float_as_uint(McT[(ni * 8 + g) * OH_KPITCH + kk + t + 4]);
        }
        #pragma unroll
        for (int mi = 0; mi < 2; mi++)
            #pragma unroll
            for (int ni = 0; ni < 8; ni++)
                mma_tf32_16x8x8(acc[mi][ni][0], acc[mi][ni][1],
                                acc[mi][ni][2], acc[mi][ni][3],
                                af[mi][0], af[mi][1], af[mi][2], af[mi][3],
                                bf[ni][0], bf[ni][1]);
    }

    const float cadd = -STEP_F * LAMBD_F;
    #pragma unroll
    for (int mi = 0; mi < 2; mi++) {
        #pragma unroll
        for (int ni = 0; ni < 8; ni++) {
            const int d0 = ni * 8 + 2 * t;       // even
            const int c16 = d0 & 15;
            const int pos = (d0 & ~15) + 4 * ((c16 & 7) >> 1) + 2 * (c16 >> 3);
            #pragma unroll
            for (int half = 0; half < 2; half++) {
                const int tok = b * NSEQ + n0 + mrow0 + mi * 16 + g + half * 8;
                const __half2 vh = *(const __half2*)(
                    g_qkvh + (size_t)tok * C3 + 1536 + h * 64 + d0);
                const float2 v = __half22float2(vh);
                const float r0 = fmaxf(v.x + acc[mi][ni][half * 2 + 0] + cadd, 0.0f);
                const float r1 = fmaxf(v.y + acc[mi][ni][half * 2 + 1] + cadd, 0.0f);
                __half2* dst = (__half2*)(g_aoh + (size_t)tok * CDIM + h * 64 + pos);
                *dst = __floats2half2_rn(r0, r1);
            }
        }
    }
}

// ---------------------------------------------------------------------------
extern "C" void kernel_launch(void* const* d_in, const int* in_sizes, int n_in,
                              void* d_out, int out_size)
{
    const float* x     = (const float*)d_in[0];
    const float* Wqkv  = (const float*)d_in[1];
    const float* Wproj = (const float*)d_in[2];
    const float* bproj = (const float*)d_in[3];
    float* out = (float*)d_out;

    __half* qkvh; cudaGetSymbolAddress((void**)&qkvh, g_qkvh);
    __half* aoh;  cudaGetSymbolAddress((void**)&aoh,  g_aoh);
    __half* xh;   cudaGetSymbolAddress((void**)&xh,   g_xh);
    __half* wqh;  cudaGetSymbolAddress((void**)&wqh,  g_wqkvh);
    __half* wph;  cudaGetSymbolAddress((void**)&wph,  g_wprojh);

    cudaFuncSetAttribute((const void*)gemm_f16_pipe<true, 128>,
                         cudaFuncAttributeMaxDynamicSharedMemorySize,
                         HGSMEM(128));
    cudaFuncSetAttribute((const void*)gemm_f16_pipe<false, 64>,
                         cudaFuncAttributeMaxDynamicSharedMemorySize,
                         HGSMEM(64));
    cudaFuncSetAttribute(outhead_mma_kernel,
                         cudaFuncAttributeMaxDynamicSharedMemorySize,
                         OH_SMEM_BYTES);

    // 0. Convert + K-permute all GEMM operands to fp16
    round_perm_kernel<<<(HG3 + 255) / 256, 256>>>(x, Wqkv, Wproj);

    // 1. qkv = x @ Wqkv^T  (fp16 MMA, fp16 output, 128x128 tiles)
    gemm_f16_pipe<true, 128><<<dim3(C3 / 128, TOKENS / 128), 128, HGSMEM(128)>>>(
        xh, wqh, nullptr, qkvh, TOKENS, C3, CDIM);
    // 2. Per-head moments (fp16 mma + ldmatrix, fused q/k normalization)
    moments_mma_kernel<<<dim3(BH, MCH), 192>>>();
    // 3. Fused reduce + combine -> Mc
    combine_fused_kernel<<<BH, 256>>>();
    // 4. relu(V + norm(K)@Mc - STEP*LAMBD), fp16 K-permuted output
    outhead_mma_kernel<<<dim3(NSEQ / 128, BH), 128, OH_SMEM_BYTES>>>();
    // 5. out = ao @ Wproj^T + bproj  (fp16 MMA, fp32 output, 128x64 tiles)
    gemm_f16_pipe<false, 64><<<dim3(CDIM / 64, TOKENS / 128), 128, HGSMEM(64)>>>(
        aoh, wph, bproj, out, TOKENS, CDIM, CDIM);
}

// round 16
// speedup vs baseline: 1.4436x; 1.4436x over previous
#include <cuda_runtime.h>
#include <cuda_fp16.h>
#include <cstdint>
#include <math.h>

// Problem constants
#define BATCH   2
#define NSEQ    2048
#define CDIM    768
#define HEADS_H 12
#define DHEAD   64
#define TOKENS  (BATCH * NSEQ)          // 4096
#define C3      (3 * CDIM)              // 2304
#define BH      (BATCH * HEADS_H)       // 24
#define MCH     16                      // moments token-split chunks

#define SCALE_F 0.125f
#define STEP_F  0.1f
#define LAMBD_F 0.5f
#define EPS_F   1e-12f

// Scratch (static device globals — no allocation)
__device__ __half g_qkvh[TOKENS * C3];  // qkv in fp16 (raw; norm fused downstream)
__device__ __half g_mparth[MCH * BH * 3 * DHEAD * DHEAD];   // fp16 partials
__device__ float  g_msum[BH * 3 * DHEAD * DHEAD];
__device__ float  g_mc[BH * DHEAD * DHEAD];
__device__ __half g_aoh[TOKENS * CDIM];     // fp16, K-permuted
__device__ __half g_xh[TOKENS * CDIM];      // fp16, K-permuted
__device__ __half g_wqkvh[C3 * CDIM];
__device__ __half g_wprojh[CDIM * CDIM];

__device__ __forceinline__ uint32_t f2tf32(float f) {
    uint32_t u;
    asm("cvt.rna.tf32.f32 %0, %1;" : "=r"(u) : "f"(f));
    return u;
}
__device__ __forceinline__ float rtf(float f) {
    return __uint_as_float(f2tf32(f));
}
__device__ __forceinline__ uint32_t smem_u32(const void* p) {
    uint32_t a;
    asm("{ .reg .u64 t; cvta.to.shared.u64 t, %1; cvt.u32.u64 %0, t; }"
        : "=r"(a) : "l"(p));
    return a;
}
__device__ __forceinline__ uint32_t h2u(float a, float b) {
    __half2 h = __floats2half2_rn(a, b);
    return *reinterpret_cast<uint32_t*>(&h);
}
__device__ __forceinline__ float2 u2f2(uint32_t u) {
    return __half22float2(*reinterpret_cast<__half2*>(&u));
}
__device__ __forceinline__ void ldsm_x4_trans(
    uint32_t& r0, uint32_t& r1, uint32_t& r2, uint32_t& r3, uint32_t addr)
{
    asm volatile("ldmatrix.sync.aligned.m8n8.x4.trans.shared.b16 "
                 "{%0,%1,%2,%3}, [%4];"
                 : "=r"(r0), "=r"(r1), "=r"(r2), "=r"(r3) : "r"(addr));
}

// fp16 m16n8k16 MMA, fp32 accumulate
__device__ __forceinline__ void mma_f16_16x8x16(
    float& c0, float& c1, float& c2, float& c3,
    uint32_t a0, uint32_t a1, uint32_t a2, uint32_t a3,
    uint32_t b0, uint32_t b1)
{
    asm volatile(
        "mma.sync.aligned.m16n8k16.row.col.f32.f16.f16.f32 "
        "{%0,%1,%2,%3}, {%4,%5,%6,%7}, {%8,%9}, {%0,%1,%2,%3};"
        : "+f"(c0), "+f"(c1), "+f"(c2), "+f"(c3)
        : "r"(a0), "r"(a1), "r"(a2), "r"(a3), "r"(b0), "r"(b1));
}
// tf32 m16n8k8 MMA (outhead path)
__device__ __forceinline__ void mma_tf32_16x8x8(
    float& c0, float& c1, float& c2, float& c3,
    uint32_t a0, uint32_t a1, uint32_t a2, uint32_t a3,
    uint32_t b0, uint32_t b1)
{
    asm volatile(
        "mma.sync.aligned.m16n8k8.row.col.f32.tf32.tf32.f32 "
        "{%0,%1,%2,%3}, {%4,%5,%6,%7}, {%8,%9}, {%0,%1,%2,%3};"
        : "+f"(c0), "+f"(c1), "+f"(c2), "+f"(c3)
        : "r"(a0), "r"(a1), "r"(a2), "r"(a3), "r"(b0), "r"(b1));
}

// ---------------------------------------------------------------------------
// Fused fp32->fp16 convert + 16-wide K-permute for x, Wqkv, Wproj.
// Output order per 16-group: [0,1,8,9,2,3,10,11,4,5,12,13,6,7,14,15]
// ---------------------------------------------------------------------------
#define HG1 (TOKENS * CDIM / 16)             // 196608
#define HG2 (HG1 + C3 * CDIM / 16)           // 307200
#define HG3 (HG2 + CDIM * CDIM / 16)         // 344064

__global__ void __launch_bounds__(256) round_perm_kernel(
    const float* __restrict__ x, const float* __restrict__ wq,
    const float* __restrict__ wp)
{
    const int gidx = blockIdx.x * 256 + threadIdx.x;
    const float* src; __half* dst; int off;
    if (gidx < HG1)      { src = x;  dst = g_xh;     off = gidx; }
    else if (gidx < HG2) { src = wq; dst = g_wqkvh;  off = gidx - HG1; }
    else if (gidx < HG3) { src = wp; dst = g_wprojh; off = gidx - HG2; }
    else return;

    const float4* s4 = (const float4*)(src) + off * 4;
    const float4 f0 = s4[0];
    const float4 f1 = s4[1];
    const float4 f2 = s4[2];
    const float4 f3 = s4[3];

    uint4 u0, u1;
    u0.x = h2u(f0.x, f0.y);  u0.y = h2u(f2.x, f2.y);
    u0.z = h2u(f0.z, f0.w);  u0.w = h2u(f2.z, f2.w);
    u1.x = h2u(f1.x, f1.y);  u1.y = h2u(f3.x, f3.y);
    u1.z = h2u(f1.z, f1.w);  u1.w = h2u(f3.z, f3.w);
    uint4* d4 = (uint4*)(dst + (size_t)off * 16);
    d4[0] = u0;
    d4[1] = u1;
}

// ---------------------------------------------------------------------------
// fp16 mma.sync NT GEMM, cp.async 4-stage pipeline, K-PERMUTED fp16 operands.
// CTA 128x128, 4 warps, warp tile 64x64, K-chunk 32, pitch 48 halves.
// HOUT=true: write fp16 (no bias). HOUT=false: write fp32 (+bias).
// ---------------------------------------------------------------------------
#define HP        48
#define HSTAGES   4
#define HSTG_B    (128 * HP * 2)
#define HGSMEM    (HSTAGES * HSTG_B * 2)      // 98304

template<bool HOUT>
__global__ void __launch_bounds__(128, 2) gemm_f16_pipe(
    const __half* __restrict__ A, const __half* __restrict__ Bw,
    const float* __restrict__ bias, void* __restrict__ Cv,
    int M, int N, int K)
{
    extern __shared__ __half hsm[];
    __half* As = hsm;
    __half* Bs = hsm + HSTAGES * 128 * HP;

    const int tid  = threadIdx.x;
    const int wid  = tid >> 5;
    const int lane = tid & 31;
    const int g    = lane >> 2;
    const int t    = lane & 3;
    const int row0 = blockIdx.y * 128;
    const int col0 = blockIdx.x * 128;
    const int wm0  = (wid >> 1) * 64;
    const int wn0  = (wid & 1) * 64;

    float acc[4][8][4];
    #pragma unroll
    for (int mi = 0; mi < 4; mi++)
        #pragma unroll
        for (int ni = 0; ni < 8; ni++)
            #pragma unroll
            for (int c = 0; c < 4; c++) acc[mi][ni][c] = 0.0f;

    const int lrow = tid >> 2;            // 0..31
    const int lseg = (tid & 3) << 3;      // 0,8,16,24 halves

    const __half* aptr = A  + (size_t)(row0 + lrow) * K + lseg;
    const __half* bptr = Bw + (size_t)(col0 + lrow) * K + lseg;
    const uint32_t a_sb = smem_u32(As) + (lrow * HP + lseg) * 2;
    const uint32_t b_sb = smem_u32(Bs) + (lrow * HP + lseg) * 2;

    const int nc = K >> 5;

    #pragma unroll
    for (int s = 0; s < HSTAGES - 1; s++) {
        const int k0 = s << 5;
        #pragma unroll
        for (int i = 0; i < 4; i++) {
            const uint32_t so = s * HSTG_B + i * 32 * HP * 2;
            asm volatile("cp.async.cg.shared.global [%0], [%1], 16;"
                :: "r"(a_sb + so), "l"(aptr + (size_t)i * 32 * K + k0) : "memory");
            asm volatile("cp.async.cg.shared.global [%0], [%1], 16;"
                :: "r"(b_sb + so), "l"(bptr + (size_t)i * 32 * K + k0) : "memory");
        }
        asm volatile("cp.async.commit_group;" ::: "memory");
    }

    for (int c = 0; c < nc; c++) {
        asm volatile("cp.async.wait_group %0;" :: "n"(HSTAGES - 2) : "memory");
        __syncthreads();

        const int cn = c + HSTAGES - 1;
        if (cn < nc) {
            const int s  = cn & (HSTAGES - 1);
            const int k0 = cn << 5;
            #pragma unroll
            for (int i = 0; i < 4; i++) {
                const uint32_t so = s * HSTG_B + i * 32 * HP * 2;
                asm volatile("cp.async.cg.shared.global [%0], [%1], 16;"
                    :: "r"(a_sb + so), "l"(aptr + (size_t)i * 32 * K + k0) : "memory");
                asm volatile("cp.async.cg.shared.global [%0], [%1], 16;"
                    :: "r"(b_sb + so), "l"(bptr + (size_t)i * 32 * K + k0) : "memory");
            }
        }
        asm volatile("cp.async.commit_group;" ::: "memory");

        const __half* as = As + (c & (HSTAGES - 1)) * 128 * HP;
        const __half* bs = Bs + (c & (HSTAGES - 1)) * 128 * HP;
        #pragma unroll
        for (int kk = 0; kk < 2; kk++) {
            const int ko = kk * 16 + t * 4;
            uint32_t af[4][4], bf[8][2];
            #pragma unroll
            for (int mi = 0; mi < 4; mi++) {
                const int mrow = wm0 + mi * 16;
                const uint2 av0 = *(const uint2*)(as + (mrow + g)     * HP + ko);
                const uint2 av1 = *(const uint2*)(as + (mrow + g + 8) * HP + ko);
                af[mi][0] = av0.x; af[mi][2] = av0.y;
                af[mi][1] = av1.x; af[mi][3] = av1.y;
            }
            #pragma unroll
            for (int ni = 0; ni < 8; ni++) {
                const uint2 bv = *(const uint2*)(bs + (wn0 + ni * 8 + g) * HP + ko);
                bf[ni][0] = bv.x; bf[ni][1] = bv.y;
            }
            #pragma unroll
            for (int mi = 0; mi < 4; mi++)
                #pragma unroll
                for (int ni = 0; ni < 8; ni++)
                    mma_f16_16x8x16(acc[mi][ni][0], acc[mi][ni][1],
                                    acc[mi][ni][2], acc[mi][ni][3],
                                    af[mi][0], af[mi][1], af[mi][2], af[mi][3],
                                    bf[ni][0], bf[ni][1]);
        }
    }

    #pragma unroll
    for (int mi = 0; mi < 4; mi++) {
        #pragma unroll
        for (int ni = 0; ni < 8; ni++) {
            const int col = col0 + wn0 + ni * 8 + 2 * t;
            const int r0 = row0 + wm0 + mi * 16 + g;
            if (HOUT) {
                __half* C = (__half*)Cv;
                *(__half2*)(C + (size_t)r0 * N + col) =
                    __floats2half2_rn(acc[mi][ni][0], acc[mi][ni][1]);
                *(__half2*)(C + (size_t)(r0 + 8) * N + col) =
                    __floats2half2_rn(acc[mi][ni][2], acc[mi][ni][3]);
            } else {
                float* C = (float*)Cv;
                float b0 = 0.f, b1 = 0.f;
                if (bias) { b0 = bias[col]; b1 = bias[col + 1]; }
                *(float2*)(C + (size_t)r0 * N + col) =
                    make_float2(acc[mi][ni][0] + b0, acc[mi][ni][1] + b1);
                *(float2*)(C + (size_t)(r0 + 8) * N + col) =
                    make_float2(acc[mi][ni][2] + b0, acc[mi][ni][3] + b1);
            }
        }
    }
}

// ---------------------------------------------------------------------------
// Moments via fp16 mma + ldmatrix.trans, FUSED q/k L2-normalization.
// Per (b,h,chunk of 128 tokens): partial M1=K^T V, M2=Q^T V, M3=Q^T Q.
// grid (BH, MCH), 192 threads. fp16 partials to g_mparth.
// ---------------------------------------------------------------------------
#define MTOK (NSEQ / MCH)                // 128 tokens per chunk
#define MNIT (MTOK / 32)                 // 4 iters of 32 tokens
#define TPITCH 72                        // halves per smem row

__global__ void __launch_bounds__(192, 2) moments_mma_kernel()
{
    __shared__ __half TQ[2][32][TPITCH];
    __shared__ __half TK[2][32][TPITCH];
    __shared__ __half TV[2][32][TPITCH];

    const int bh = blockIdx.x;
    const int ch = blockIdx.y;
    const int b = bh / HEADS_H, h = bh % HEADS_H;
    const int tid  = threadIdx.x;
    const int wid  = tid >> 5;
    const int lane = tid & 31;
    const int g    = lane >> 2;
    const int t    = lane & 3;
    const int o    = wid >> 1;
    const int mhalf = (wid & 1) * 32;

    const int mat  = tid >> 6;
    const int trow = (tid & 63) >> 1;
    const int dh   = (tid & 1) * 32;

    const size_t base = (size_t)(b * NSEQ + ch * MTOK) * C3
                      + mat * 768 + h * 64 + dh;

    const int a_tok = ((lane >> 4) << 3) + (lane & 7);
    const int a_d   = ((lane >> 3) & 1) << 3;
    const int b_tok = (((lane >> 3) & 1) << 3) + (lane & 7);
    const int b_d   = (lane >> 4) << 3;

    float acc[2][8][4];
    #pragma unroll
    for (int mi = 0; mi < 2; mi++)
        #pragma unroll
        for (int ni = 0; ni < 8; ni++)
            #pragma unroll
            for (int c = 0; c < 4; c++) acc[mi][ni][c] = 0.0f;

    uint4 r[4];
    {
        const __half* src = g_qkvh + base + (size_t)trow * C3;
        #pragma unroll
        for (int j = 0; j < 4; j++) r[j] = ((const uint4*)src)[j];
    }

    for (int it = 0; it < MNIT; it++) {
        float inv = 1.0f;
        if (mat < 2) {
            float ss = 0.f;
            #pragma unroll
            for (int j = 0; j < 4; j++) {
                const uint32_t* u = &r[j].x;
                #pragma unroll
                for (int q = 0; q < 4; q++) {
                    const float2 f = u2f2(u[q]);
                    ss += f.x * f.x + f.y * f.y;
                }
            }
            ss += __shfl_xor_sync(0xffffffffu, ss, 1);
            inv = 1.0f / fmaxf(sqrtf(ss), EPS_F);
        }
        {
            __half* Td = ((mat == 0) ? TQ[it & 1]
                        : (mat == 1) ? TK[it & 1] : TV[it & 1])[trow] + dh;
            #pragma unroll
            for (int j = 0; j < 4; j++) {
                const uint32_t* u = &r[j].x;
                uint4 w;
                const float2 f0 = u2f2(u[0]);
                const float2 f1 = u2f2(u[1]);
                const float2 f2 = u2f2(u[2]);
                const float2 f3 = u2f2(u[3]);
                w.x = h2u(f0.x * inv, f0.y * inv);
                w.y = h2u(f1.x * inv, f1.y * inv);
                w.z = h2u(f2.x * inv, f2.y * inv);
                w.w = h2u(f3.x * inv, f3.y * inv);
                ((uint4*)Td)[j] = w;
            }
        }
        uint4 rn[4];
        if (it + 1 < MNIT) {
            const __half* src = g_qkvh + base + (size_t)((it + 1) * 32 + trow) * C3;
            #pragma unroll
            for (int j = 0; j < 4; j++) rn[j] = ((const uint4*)src)[j];
        }
        __syncthreads();

        const uint32_t am = smem_u32((o == 0) ? TK[it & 1] : TQ[it & 1]);
        const uint32_t bm = smem_u32((o == 2) ? TQ[it & 1] : TV[it & 1]);
        #pragma unroll
        for (int ks = 0; ks < 2; ks++) {
            const int tokb = ks * 16;
            uint32_t af[2][4], bf[8][2];
            #pragma unroll
            for (int mi = 0; mi < 2; mi++) {
                const uint32_t addr = am +
                    ((tokb + a_tok) * TPITCH + mhalf + mi * 16 + a_d) * 2;
                ldsm_x4_trans(af[mi][0], af[mi][1], af[mi][2], af[mi][3], addr);
            }
            #pragma unroll
            for (int j = 0; j < 4; j++) {
                const uint32_t addr = bm +
                    ((tokb + b_tok) * TPITCH + j * 16 + b_d) * 2;
                ldsm_x4_trans(bf[2 * j][0], bf[2 * j][1],
                              bf[2 * j + 1][0], bf[2 * j + 1][1], addr);
            }
            #pragma unroll
            for (int mi = 0; mi < 2; mi++)
                #pragma unroll
                for (int ni = 0; ni < 8; ni++)
                    mma_f16_16x8x16(acc[mi][ni][0], acc[mi][ni][1],
                                    acc[mi][ni][2], acc[mi][ni][3],
                                    af[mi][0], af[mi][1], af[mi][2], af[mi][3],
                                    bf[ni][0], bf[ni][1]);
        }
        #pragma unroll
        for (int j = 0; j < 4; j++) r[j] = rn[j];
    }

    __half* outp = g_mparth + ((size_t)(ch * BH + bh) * 3 + o) * 4096;
    #pragma unroll
    for (int mi = 0; mi < 2; mi++) {
        #pragma unroll
        for (int ni = 0; ni < 8; ni++) {
            const int row = mhalf + mi * 16 + g;
            const int col = ni * 8 + 2 * t;
            *(__half2*)(outp + row * 64 + col) =
                __floats2half2_rn(acc[mi][ni][0], acc[mi][ni][1]);
            *(__half2*)(outp + (row + 8) * 64 + col) =
                __floats2half2_rn(acc[mi][ni][2], acc[mi][ni][3]);
        }
    }
}

// ---------------------------------------------------------------------------
// Parallel reduce of fp16 g_mparth over MCH chunks -> fp32 g_msum
// 4 halves per thread, grid 288 (2x parallelism vs R13).
// ---------------------------------------------------------------------------
#define RED_H4 (BH * 3 * DHEAD * DHEAD / 4)   // 73728

__global__ void __launch_bounds__(256) reduce_mpart_kernel()
{
    const int f4 = blockIdx.x * 256 + threadIdx.x;
    if (f4 >= RED_H4) return;
    const int elem = f4 * 4;
    const int bh_o = elem >> 12;          // bh*3+o  (0..71)
    const int i    = elem & 4095;

    float s0 = 0.f, s1 = 0.f, s2 = 0.f, s3 = 0.f;
    #pragma unroll
    for (int ch = 0; ch < MCH; ch++) {
        const uint2 v = *(const uint2*)(
            g_mparth + ((size_t)(ch * 72 + bh_o)) * 4096 + i);
        const float2 f0 = u2f2(v.x);
        const float2 f1 = u2f2(v.y);
        s0 += f0.x; s1 += f0.y; s2 += f1.x; s3 += f1.y;
    }
    *(float4*)(g_msum + (size_t)bh_o * 4096 + i) = make_float4(s0, s1, s2, s3);
}

// ---------------------------------------------------------------------------
// Small combine: Mc = STEP*(SCALE*M2 - SCALE^2*M3@M1)
// ---------------------------------------------------------------------------
__global__ void __launch_bounds__(256) combine_small_kernel()
{
    const int bh  = blockIdx.x;
    const int tid = threadIdx.x;
    __shared__ float m1s[4096];
    __shared__ float m3s[4096];

    const float* src = g_msum + (size_t)bh * 3 * 4096;
    #pragma unroll
    for (int i = 0; i < 4; i++) {
        const int o4 = tid + i * 256;
        ((float4*)m1s)[o4] = ((const float4*)src)[o4];
        ((float4*)m3s)[o4] = ((const float4*)(src + 8192))[o4];
    }
    __syncthreads();

    const int tr = tid >> 4, tc = tid & 15;
    float p[4][4];
    #pragma unroll
    for (int i = 0; i < 4; i++)
        #pragma unroll
        for (int j = 0; j < 4; j++) p[i][j] = 0.f;

    for (int e = 0; e < 64; e++) {
        float a[4], bb[4];
        #pragma unroll
        for (int i = 0; i < 4; i++) a[i] = m3s[(tr * 4 + i) * 64 + e];
        #pragma unroll
        for (int j = 0; j < 4; j++) bb[j] = m1s[e * 64 + tc * 4 + j];
        #pragma unroll
        for (int i = 0; i < 4; i++)
            #pragma unroll
            for (int j = 0; j < 4; j++) p[i][j] += a[i] * bb[j];
    }

    const float c1 = STEP_F * SCALE_F;
    const float c2 = STEP_F * SCALE_F * SCALE_F;
    const float* m2p = src + 4096;
    #pragma unroll
    for (int i = 0; i < 4; i++)
        #pragma unroll
        for (int j = 0; j < 4; j++) {
            const int idx = (tr * 4 + i) * 64 + (tc * 4 + j);
            g_mc[(size_t)bh * 4096 + idx] = c1 * m2p[idx] - c2 * p[i][j];
        }
}

// ---------------------------------------------------------------------------
// outhead via tf32 mma with FUSED K-normalization; fp16 qkv input.
// Output: fp16 K-permuted (16-wide perm) half2 stores into g_aoh.
// ---------------------------------------------------------------------------
#define OH_KPITCH   68
#define OH_KS_FL    (128 * OH_KPITCH)
#define OH_MC_FL    (64 * OH_KPITCH)
#define OH_SMEM_BYTES ((OH_KS_FL + OH_MC_FL) * 4)   // 52224

__global__ void __launch_bounds__(128) outhead_mma_kernel()
{
    extern __shared__ float osm[];
    float* Ks  = osm;
    float* McT = osm + OH_KS_FL;

    const int bh   = blockIdx.y;
    const int tile = blockIdx.x;
    const int b = bh / HEADS_H, h = bh % HEADS_H;
    const int tid  = threadIdx.x;
    const int wid  = tid >> 5;
    const int lane = tid & 31;
    const int g    = lane >> 2;
    const int t    = lane & 3;
    const int n0   = tile * 128;

    {
        const int d1  = tid >> 1;
        const int d2g = (tid & 1) * 32;
        const float* src = g_mc + (size_t)bh * 4096 + d1 * 64 + d2g;
        #pragma unroll
        for (int j = 0; j < 8; j++) {
            float4 v = *(const float4*)(src + j * 4);
            McT[(d2g + j * 4 + 0) * OH_KPITCH + d1] = rtf(v.x);
            McT[(d2g + j * 4 + 1) * OH_KPITCH + d1] = rtf(v.y);
            McT[(d2g + j * 4 + 2) * OH_KPITCH + d1] = rtf(v.z);
            McT[(d2g + j * 4 + 3) * OH_KPITCH + d1] = rtf(v.w);
        }
    }
    {
        const __half* src = g_qkvh + (size_t)(b * NSEQ + n0 + tid) * C3 + 768 + h * 64;
        float kv[64];
        float ss = 0.f;
        #pragma unroll
        for (int j = 0; j < 8; j++) {
            const uint4 r = *(const uint4*)(src + j * 8);
            const uint32_t* u = &r.x;
            #pragma unroll
            for (int q = 0; q < 4; q++) {
                const float2 f = u2f2(u[q]);
                kv[j * 8 + q * 2]     = f.x;
                kv[j * 8 + q * 2 + 1] = f.y;
                ss += f.x * f.x + f.y * f.y;
            }
        }
        const float inv = 1.0f / fmaxf(sqrtf(ss), EPS_F);
        #pragma unroll
        for (int j = 0; j < 64; j++)
            Ks[tid * OH_KPITCH + j] = rtf(kv[j] * inv);
    }
    __syncthreads();

    const int mrow0 = wid * 32;
    float acc[2][8][4];
    #pragma unroll
    for (int mi = 0; mi < 2; mi++)
        #pragma unroll
        for (int ni = 0; ni < 8; ni++)
            #pragma unroll
            for (int c = 0; c < 4; c++) acc[mi][ni][c] = 0.0f;

    #pragma unroll
    for (int kk = 0; kk < 64; kk += 8) {
        uint32_t af[2][4], bf[8][2];
        #pragma unroll
        for (int mi = 0; mi < 2; mi++) {
            const int mrow = mrow0 + mi * 16;
            af[mi][0] = __float_as_uint(Ks[(mrow + g)     * OH_KPITCH + kk + t]);
            af[mi][1] = __float_as_uint(Ks[(mrow + g + 8) * OH_KPITCH + kk + t]);
            af[mi][2] = __float_as_uint(Ks[(mrow + g)     * OH_KPITCH + kk + t + 4]);
            af[mi][3] = __float_as_uint(Ks[(mrow + g + 8) * OH_KPITCH + kk + t + 4]);
        }
        #pragma unroll
        for (int ni = 0; ni < 8; ni++) {
            bf[ni][0] = __float_as_uint(McT[(ni * 8 + g) * OH_KPITCH + kk + t]);
            bf[ni][1] = __float_as_uint(McT[(ni * 8 + g) * OH_KPITCH + kk + t + 4]);
        }
        #pragma unroll
        for (int mi = 0; mi < 2; mi++)
            #pragma unroll
            for (int ni = 0; ni < 8; ni++)
                mma_tf32_16x8x8(acc[mi][ni][0], acc[mi][ni][1],
                                acc[mi][ni][2], acc[mi][ni][3],
                                af[mi][0], af[mi][1], af[mi][2], af[mi][3],
                                bf[ni][0], bf[ni][1]);
    }

    const float cadd = -STEP_F * LAMBD_F;
    #pragma unroll
    for (int mi = 0; mi < 2; mi++) {
        #pragma unroll
        for (int ni = 0; ni < 8; ni++) {
            const int d0 = ni * 8 + 2 * t;       // even
            const int c16 = d0 & 15;
            const int pos = (d0 & ~15) + 4 * ((c16 & 7) >> 1) + 2 * (c16 >> 3);
            #pragma unroll
            for (int half = 0; half < 2; half++) {
                const int tok = b * NSEQ + n0 + mrow0 + mi * 16 + g + half * 8;
                const __half2 vh = *(const __half2*)(
                    g_qkvh + (size_t)tok * C3 + 1536 + h * 64 + d0);
                const float2 v = __half22float2(vh);
                const float r0 = fmaxf(v.x + acc[mi][ni][half * 2 + 0] + cadd, 0.0f);
                const float r1 = fmaxf(v.y + acc[mi][ni][half * 2 + 1] + cadd, 0.0f);
                __half2* dst = (__half2*)(g_aoh + (size_t)tok * CDIM + h * 64 + pos);
                *dst = __floats2half2_rn(r0, r1);
            }
        }
    }
}

// ---------------------------------------------------------------------------
extern "C" void kernel_launch(void* const* d_in, const int* in_sizes, int n_in,
                              void* d_out, int out_size)
{
    const float* x     = (const float*)d_in[0];
    const float* Wqkv  = (const float*)d_in[1];
    const float* Wproj = (const float*)d_in[2];
    const float* bproj = (const float*)d_in[3];
    float* out = (float*)d_out;

    __half* qkvh; cudaGetSymbolAddress((void**)&qkvh, g_qkvh);
    __half* aoh;  cudaGetSymbolAddress((void**)&aoh,  g_aoh);
    __half* xh;   cudaGetSymbolAddress((void**)&xh,   g_xh);
    __half* wqh;  cudaGetSymbolAddress((void**)&wqh,  g_wqkvh);
    __half* wph;  cudaGetSymbolAddress((void**)&wph,  g_wprojh);

    cudaFuncSetAttribute(gemm_f16_pipe<true>,
                         cudaFuncAttributeMaxDynamicSharedMemorySize, HGSMEM);
    cudaFuncSetAttribute(gemm_f16_pipe<false>,
                         cudaFuncAttributeMaxDynamicSharedMemorySize, HGSMEM);
    cudaFuncSetAttribute(outhead_mma_kernel,
                         cudaFuncAttributeMaxDynamicSharedMemorySize,
                         OH_SMEM_BYTES);

    // 0. Convert + K-permute all GEMM operands to fp16
    round_perm_kernel<<<(HG3 + 255) / 256, 256>>>(x, Wqkv, Wproj);

    // 1. qkv = x @ Wqkv^T  (fp16 MMA, fp16 output)
    gemm_f16_pipe<true><<<dim3(C3 / 128, TOKENS / 128), 128, HGSMEM>>>(
        xh, wqh, nullptr, qkvh, TOKENS, C3, CDIM);
    // 2. Per-head moments (fp16 mma + ldmatrix, fused q/k normalization)
    moments_mma_kernel<<<dim3(BH, MCH), 192>>>();
    // 3a. Parallel reduce of fp16 chunk partials (grid 288)
    reduce_mpart_kernel<<<(RED_H4 + 255) / 256, 256>>>();
    // 3b. Mc = STEP*(SCALE*M2 - SCALE^2 * M3@M1)
    combine_small_kernel<<<BH, 256>>>();
    // 4. relu(V + norm(K)@Mc - STEP*LAMBD), fp16 K-permuted output
    outhead_mma_kernel<<<dim3(NSEQ / 128, BH), 128, OH_SMEM_BYTES>>>();
    // 5. out = ao @ Wproj^T + bproj  (fp16 MMA, fp32 output)
    gemm_f16_pipe<false><<<dim3(CDIM / 128, TOKENS / 128), 128, HGSMEM>>>(
        aoh, wph, bproj, out, TOKENS, CDIM, CDIM);
}